// round 7
// baseline (speedup 1.0000x reference)
#include <cuda_runtime.h>
#include <math.h>
#include <stdint.h>

#define D_MODEL 1024
#define D_FF    4096
#define BATCH   4
#define SEQ     2048
#define NTOK    (BATCH * SEQ)   // 8192

// ---------------- scratch (allocation-free: __device__ globals) ----------------
__device__ float g_norm1[(size_t)NTOK * D_MODEL];
__device__ float g_norm1t[(size_t)NTOK * D_MODEL];      // per-batch [D][S]
__device__ float g_scores[(size_t)BATCH * SEQ * SEQ];
__device__ float g_attn[(size_t)NTOK * D_MODEL];
__device__ float g_x[(size_t)NTOK * D_MODEL];
__device__ float g_norm2[(size_t)NTOK * D_MODEL];
__device__ float g_h[(size_t)NTOK * D_FF];
__device__ float g_w1t[(size_t)D_FF * D_MODEL];
__device__ float g_w2t[(size_t)D_MODEL * D_FF];

// tf32 round-to-nearest (applied at producer stores; GEMM reads raw bits)
__device__ __forceinline__ float tf32r(float x) {
    uint32_t u;
    asm("cvt.rna.tf32.f32 %0, %1;" : "=r"(u) : "f"(x));
    return __uint_as_float(u);
}

// ---------------- reductions ----------------
__device__ __forceinline__ float block_sum(float v, float* sh) {
    int lane = threadIdx.x & 31, w = threadIdx.x >> 5;
    #pragma unroll
    for (int o = 16; o; o >>= 1) v += __shfl_down_sync(0xffffffffu, v, o);
    if (lane == 0) sh[w] = v;
    __syncthreads();
    if (w == 0) {
        float t = (lane < 8) ? sh[lane] : 0.f;
        #pragma unroll
        for (int o = 4; o; o >>= 1) t += __shfl_down_sync(0xffffffffu, t, o);
        if (lane == 0) sh[0] = t;
    }
    __syncthreads();
    float r = sh[0];
    __syncthreads();
    return r;
}

__device__ __forceinline__ float block_max(float v, float* sh) {
    int lane = threadIdx.x & 31, w = threadIdx.x >> 5;
    #pragma unroll
    for (int o = 16; o; o >>= 1) v = fmaxf(v, __shfl_down_sync(0xffffffffu, v, o));
    if (lane == 0) sh[w] = v;
    __syncthreads();
    if (w == 0) {
        float t = (lane < 8) ? sh[lane] : -3.4e38f;
        #pragma unroll
        for (int o = 4; o; o >>= 1) t = fmaxf(t, __shfl_down_sync(0xffffffffu, t, o));
        if (lane == 0) sh[0] = t;
    }
    __syncthreads();
    float r = sh[0];
    __syncthreads();
    return r;
}

// ---------------- LayerNorm (stores tf32-rounded) ----------------
__global__ __launch_bounds__(256) void ln_kernel(
    const float* __restrict__ in, const float* __restrict__ gamma,
    const float* __restrict__ beta, float* __restrict__ out)
{
    __shared__ float sh[32];
    size_t row = blockIdx.x;
    const float* x = in + row * D_MODEL;
    float v[4], s = 0.f;
    #pragma unroll
    for (int i = 0; i < 4; i++) { v[i] = x[threadIdx.x + i * 256]; s += v[i]; }
    float mean = block_sum(s, sh) * (1.0f / D_MODEL);
    float q = 0.f;
    #pragma unroll
    for (int i = 0; i < 4; i++) { float d = v[i] - mean; q += d * d; }
    float var = block_sum(q, sh) * (1.0f / D_MODEL);
    float rstd = rsqrtf(var + 1e-5f);
    float* y = out + row * D_MODEL;
    #pragma unroll
    for (int i = 0; i < 4; i++) {
        int c = threadIdx.x + i * 256;
        y[c] = tf32r((v[i] - mean) * rstd * gamma[c] + beta[c]);
    }
}

// x kept full precision; norm tf32-rounded
__global__ __launch_bounds__(256) void add_ln_kernel(
    const float* __restrict__ src, const float* __restrict__ attn,
    const float* __restrict__ gamma, const float* __restrict__ beta,
    float* __restrict__ xout, float* __restrict__ nout)
{
    __shared__ float sh[32];
    size_t row = blockIdx.x;
    const float* a = src + row * D_MODEL;
    const float* b = attn + row * D_MODEL;
    float v[4], s = 0.f;
    #pragma unroll
    for (int i = 0; i < 4; i++) {
        int c = threadIdx.x + i * 256;
        v[i] = a[c] + b[c];
        s += v[i];
    }
    float* xo = xout + row * D_MODEL;
    #pragma unroll
    for (int i = 0; i < 4; i++) xo[threadIdx.x + i * 256] = v[i];
    float mean = block_sum(s, sh) * (1.0f / D_MODEL);
    float q = 0.f;
    #pragma unroll
    for (int i = 0; i < 4; i++) { float d = v[i] - mean; q += d * d; }
    float var = block_sum(q, sh) * (1.0f / D_MODEL);
    float rstd = rsqrtf(var + 1e-5f);
    float* y = nout + row * D_MODEL;
    #pragma unroll
    for (int i = 0; i < 4; i++) {
        int c = threadIdx.x + i * 256;
        y[c] = tf32r((v[i] - mean) * rstd * gamma[c] + beta[c]);
    }
}

// ---------------- softmax (stores tf32-rounded) ----------------
__global__ __launch_bounds__(256) void softmax_kernel(float* __restrict__ sc)
{
    __shared__ float sh[32];
    size_t row = blockIdx.x;
    float* p = sc + row * (size_t)SEQ;
    float v[8], m = -3.4e38f;
    #pragma unroll
    for (int i = 0; i < 8; i++) { v[i] = p[threadIdx.x + i * 256]; m = fmaxf(m, v[i]); }
    m = block_max(m, sh);
    float s = 0.f;
    #pragma unroll
    for (int i = 0; i < 8; i++) { v[i] = __expf(v[i] - m); s += v[i]; }
    s = block_sum(s, sh);
    float inv = 1.0f / s;
    #pragma unroll
    for (int i = 0; i < 8; i++) p[threadIdx.x + i * 256] = tf32r(v[i] * inv);
}

// ---------------- tiled transpose (stores tf32-rounded) ----------------
__global__ __launch_bounds__(256) void transpose_k(
    const float* __restrict__ in, float* __restrict__ out,
    int R, int C, size_t sI, size_t sO)
{
    in += blockIdx.z * sI; out += blockIdx.z * sO;
    __shared__ float t[32][33];
    int tx = threadIdx.x & 31, ty = threadIdx.x >> 5;
    int c = blockIdx.x * 32 + tx;
    int r0 = blockIdx.y * 32;
    #pragma unroll
    for (int i = 0; i < 4; i++)
        t[ty + i * 8][tx] = in[(size_t)(r0 + ty + i * 8) * C + c];
    __syncthreads();
    int rc = r0 + tx;
    int oc0 = blockIdx.x * 32;
    #pragma unroll
    for (int i = 0; i < 4; i++)
        out[(size_t)(oc0 + ty + i * 8) * R + rc] = tf32r(t[tx][ty + i * 8]);
}

// ======================= TF32 HMMA GEMM, cp.async pipeline ==================
// C[M,N] = A[M,K] @ Bt[N,K]^T. Inputs pre-rounded to tf32 by producers.
// Block 128x128, 128 threads = 4 warps (2x2), warp tile 64x64, BK=16,
// 3-stage cp.async pipeline, smem layout [row][k] with stride 20 floats
// (conflict-free fragment LDS). EPI: 0=scale 1=gelu+bias 2=bias+resid

#define BK   16
#define STG  3
#define TSTR 20
#define TILE_F (128 * TSTR)       // floats per tile
#define TILE_B (TILE_F * 4)       // bytes per tile
#define GSMEM_BYTES (2 * STG * TILE_B)   // 61440

__device__ __forceinline__ uint32_t smem_u32(const void* p) {
    uint32_t a;
    asm("{ .reg .u64 t; cvta.to.shared.u64 t, %1; cvt.u32.u64 %0, t; }" : "=r"(a) : "l"(p));
    return a;
}
__device__ __forceinline__ void cp16(uint32_t dst, const float* src) {
    asm volatile("cp.async.ca.shared.global [%0], [%1], 16;" :: "r"(dst), "l"(src));
}
__device__ __forceinline__ void cp_commit() {
    asm volatile("cp.async.commit_group;" ::: "memory");
}

__device__ __forceinline__ void mma8(float* c, const uint32_t* a, const uint32_t* b) {
    asm volatile(
        "mma.sync.aligned.m16n8k8.row.col.f32.tf32.tf32.f32 "
        "{%0,%1,%2,%3}, {%4,%5,%6,%7}, {%8,%9}, {%0,%1,%2,%3};"
        : "+f"(c[0]), "+f"(c[1]), "+f"(c[2]), "+f"(c[3])
        : "r"(a[0]), "r"(a[1]), "r"(a[2]), "r"(a[3]), "r"(b[0]), "r"(b[1]));
}

__device__ __forceinline__ float gelu_exact(float v) {
    return v * 0.5f * (1.0f + erff(v * 0.70710678118654752f));
}

template<int EPI>
__global__ __launch_bounds__(128) void gemm_cp(
    const float* __restrict__ A, const float* __restrict__ Bt, float* __restrict__ C,
    int K, int N, size_t sA, size_t sB, size_t sC,
    const float* __restrict__ bias, const float* __restrict__ resid, float scale)
{
    extern __shared__ float smbuf[];
    A += blockIdx.z * sA; Bt += blockIdx.z * sB; C += blockIdx.z * sC;
    if (EPI == 2) resid += blockIdx.z * sC;

    float* Asm = smbuf;                   // [STG][128][TSTR]
    float* Bsm = smbuf + STG * TILE_F;

    const int tid  = threadIdx.x;
    const int lane = tid & 31;
    const int warp = tid >> 5;
    const int warpM = warp >> 1;
    const int warpN = warp & 1;
    const int r  = lane >> 2;
    const int cq = lane & 3;

    const int row0 = blockIdx.y * 128;
    const int col0 = blockIdx.x * 128;

    const float* pa = A + (size_t)(row0 + tid) * K;
    const float* pb = Bt + (size_t)(col0 + tid) * K;
    const uint32_t sa0 = smem_u32(Asm) + (uint32_t)tid * (TSTR * 4);
    const uint32_t sb0 = smem_u32(Bsm) + (uint32_t)tid * (TSTR * 4);

    const int nch = K / BK;

    auto load_tile = [&](int t) {
        const int st = t % STG;
        const float* ga = pa + t * BK;
        const float* gb = pb + t * BK;
        const uint32_t da = sa0 + st * TILE_B;
        const uint32_t db = sb0 + st * TILE_B;
        #pragma unroll
        for (int i = 0; i < 4; i++) cp16(da + i * 16, ga + i * 4);
        #pragma unroll
        for (int i = 0; i < 4; i++) cp16(db + i * 16, gb + i * 4);
        cp_commit();
    };

    float acc[4][8][4] = {};

    load_tile(0);
    load_tile(1);

    for (int c = 0; c < nch; c++) {
        if (c + 1 < nch)
            asm volatile("cp.async.wait_group 1;" ::: "memory");
        else
            asm volatile("cp.async.wait_group 0;" ::: "memory");
        __syncthreads();

        const float* As2 = Asm + (c % STG) * TILE_F;
        const float* Bs2 = Bsm + (c % STG) * TILE_F;

        #pragma unroll
        for (int ks = 0; ks < 2; ks++) {
            const int c0 = ks * 8 + cq, c1 = ks * 8 + cq + 4;
            uint32_t afr[4][4], bfr[8][2];
            #pragma unroll
            for (int i = 0; i < 4; i++) {
                int m = warpM * 64 + i * 16 + r;
                afr[i][0] = __float_as_uint(As2[m * TSTR + c0]);
                afr[i][1] = __float_as_uint(As2[(m + 8) * TSTR + c0]);
                afr[i][2] = __float_as_uint(As2[m * TSTR + c1]);
                afr[i][3] = __float_as_uint(As2[(m + 8) * TSTR + c1]);
            }
            #pragma unroll
            for (int j = 0; j < 8; j++) {
                int n = warpN * 64 + j * 8 + r;
                bfr[j][0] = __float_as_uint(Bs2[n * TSTR + c0]);
                bfr[j][1] = __float_as_uint(Bs2[n * TSTR + c1]);
            }
            #pragma unroll
            for (int i = 0; i < 4; i++)
                #pragma unroll
                for (int j = 0; j < 8; j++)
                    mma8(acc[i][j], afr[i], bfr[j]);
        }
        __syncthreads();
        if (c + STG - 1 < nch) load_tile(c + STG - 1);
    }

    // ---- epilogue ----
    #pragma unroll
    for (int i = 0; i < 4; i++) {
        int mrow = row0 + warpM * 64 + i * 16 + r;
        #pragma unroll
        for (int j = 0; j < 8; j++) {
            int ncol = col0 + warpN * 64 + j * 8 + 2 * cq;
            float v0 = acc[i][j][0], v1 = acc[i][j][1];
            float v2 = acc[i][j][2], v3 = acc[i][j][3];
            if (EPI == 0) {
                v0 *= scale; v1 *= scale; v2 *= scale; v3 *= scale;
            } else {
                float bb0 = bias[ncol], bb1 = bias[ncol + 1];
                if (EPI == 1) {
                    // feeds next GEMM: round to tf32 at store
                    v0 = tf32r(gelu_exact(v0 + bb0)); v1 = tf32r(gelu_exact(v1 + bb1));
                    v2 = tf32r(gelu_exact(v2 + bb0)); v3 = tf32r(gelu_exact(v3 + bb1));
                } else {
                    size_t p0 = (size_t)mrow * N + ncol;
                    size_t p1 = (size_t)(mrow + 8) * N + ncol;
                    v0 += bb0 + resid[p0];     v1 += bb1 + resid[p0 + 1];
                    v2 += bb0 + resid[p1];     v3 += bb1 + resid[p1 + 1];
                }
            }
            size_t p0 = (size_t)mrow * N + ncol;
            size_t p1 = (size_t)(mrow + 8) * N + ncol;
            C[p0] = v0; C[p0 + 1] = v1;
            C[p1] = v2; C[p1 + 1] = v3;
        }
    }
}

// ---------------- launch ----------------
extern "C" void kernel_launch(void* const* d_in, const int* in_sizes, int n_in,
                              void* d_out, int out_size)
{
    const float* src    = (const float*)d_in[0];
    const float* gamma1 = (const float*)d_in[1];
    const float* beta1  = (const float*)d_in[2];
    const float* gamma2 = (const float*)d_in[3];
    const float* beta2  = (const float*)d_in[4];
    const float* w1     = (const float*)d_in[5];
    const float* b1     = (const float*)d_in[6];
    const float* w2     = (const float*)d_in[7];
    const float* b2     = (const float*)d_in[8];
    float* out = (float*)d_out;

    float *norm1, *norm1t, *scores, *attn, *x, *norm2, *h, *w1t, *w2t;
    cudaGetSymbolAddress((void**)&norm1, g_norm1);
    cudaGetSymbolAddress((void**)&norm1t, g_norm1t);
    cudaGetSymbolAddress((void**)&scores, g_scores);
    cudaGetSymbolAddress((void**)&attn, g_attn);
    cudaGetSymbolAddress((void**)&x, g_x);
    cudaGetSymbolAddress((void**)&norm2, g_norm2);
    cudaGetSymbolAddress((void**)&h, g_h);
    cudaGetSymbolAddress((void**)&w1t, g_w1t);
    cudaGetSymbolAddress((void**)&w2t, g_w2t);

    cudaFuncSetAttribute(gemm_cp<0>, cudaFuncAttributeMaxDynamicSharedMemorySize, GSMEM_BYTES);
    cudaFuncSetAttribute(gemm_cp<1>, cudaFuncAttributeMaxDynamicSharedMemorySize, GSMEM_BYTES);
    cudaFuncSetAttribute(gemm_cp<2>, cudaFuncAttributeMaxDynamicSharedMemorySize, GSMEM_BYTES);

    const size_t SD = (size_t)SEQ * D_MODEL;
    const size_t SS = (size_t)SEQ * SEQ;

    // weight transposes -> K-major B operands (tf32-rounded)
    transpose_k<<<dim3(D_FF / 32, D_MODEL / 32, 1), 256>>>(w1, w1t, D_MODEL, D_FF, 0, 0);
    transpose_k<<<dim3(D_MODEL / 32, D_FF / 32, 1), 256>>>(w2, w2t, D_FF, D_MODEL, 0, 0);

    // 1. norm1 = LN(src)  (tf32-rounded)
    ln_kernel<<<NTOK, 256>>>(src, gamma1, beta1, norm1);

    // 1b. norm1t[b] = norm1[b]^T
    transpose_k<<<dim3(D_MODEL / 32, SEQ / 32, BATCH), 256>>>(norm1, norm1t, SEQ, D_MODEL, SD, SD);

    // 2. scores[b] = norm1[b] @ norm1[b]^T / 32
    gemm_cp<0><<<dim3(SEQ / 128, SEQ / 128, BATCH), 128, GSMEM_BYTES>>>(
        norm1, norm1, scores, D_MODEL, SEQ, SD, SD, SS, nullptr, nullptr, 0.03125f);

    // 3. softmax rows (tf32-rounded output)
    softmax_kernel<<<BATCH * SEQ, 256>>>(scores);

    // 4. attn[b] = scores[b] @ norm1[b]   (Bt = norm1t)
    gemm_cp<0><<<dim3(D_MODEL / 128, SEQ / 128, BATCH), 128, GSMEM_BYTES>>>(
        scores, norm1t, attn, SEQ, D_MODEL, SS, SD, SD, nullptr, nullptr, 1.0f);

    // 5. x = src + attn ; norm2 = LN(x)
    add_ln_kernel<<<NTOK, 256>>>(src, attn, gamma2, beta2, x, norm2);

    // 6. h = gelu(norm2 @ w1 + b1)   (Bt = w1t)
    gemm_cp<1><<<dim3(D_FF / 128, NTOK / 128, 1), 128, GSMEM_BYTES>>>(
        norm2, w1t, h, D_MODEL, D_FF, 0, 0, 0, b1, nullptr, 1.0f);

    // 7. out = h @ w2 + b2 + x      (Bt = w2t)
    gemm_cp<2><<<dim3(D_MODEL / 128, NTOK / 128, 1), 128, GSMEM_BYTES>>>(
        h, w2t, out, D_FF, D_MODEL, 0, 0, 0, b2, x, 1.0f);

    (void)in_sizes; (void)n_in; (void)out_size;
}

// round 8
// speedup vs baseline: 1.1807x; 1.1807x over previous
#include <cuda_runtime.h>
#include <math.h>
#include <stdint.h>

#define D_MODEL 1024
#define D_FF    4096
#define BATCH   4
#define SEQ     2048
#define NTOK    (BATCH * SEQ)   // 8192

// ---------------- scratch (allocation-free: __device__ globals) ----------------
__device__ float g_norm1[(size_t)NTOK * D_MODEL];
__device__ float g_scores[(size_t)BATCH * SEQ * SEQ];
__device__ float g_attn[(size_t)NTOK * D_MODEL];
__device__ float g_x[(size_t)NTOK * D_MODEL];
__device__ float g_norm2[(size_t)NTOK * D_MODEL];
__device__ float g_h[(size_t)NTOK * D_FF];
__device__ float g_w1r[(size_t)D_MODEL * D_FF];   // tf32-rounded copy of w1
__device__ float g_w2r[(size_t)D_FF * D_MODEL];   // tf32-rounded copy of w2

// tf32 round-to-nearest (producers only; GEMM reads raw bits)
__device__ __forceinline__ float tf32r(float x) {
    uint32_t u;
    asm("cvt.rna.tf32.f32 %0, %1;" : "=r"(u) : "f"(x));
    return __uint_as_float(u);
}

// ---------------- weight rounding copy ----------------
__global__ __launch_bounds__(256) void wrnd_kernel(
    const float* __restrict__ in, float* __restrict__ out, int n)
{
    int i = blockIdx.x * 256 + threadIdx.x;
    float4 v = *(const float4*)(in + (size_t)i * 4);
    v.x = tf32r(v.x); v.y = tf32r(v.y); v.z = tf32r(v.z); v.w = tf32r(v.w);
    *(float4*)(out + (size_t)i * 4) = v;
    (void)n;
}

// ---------------- reductions ----------------
__device__ __forceinline__ float block_sum(float v, float* sh) {
    int lane = threadIdx.x & 31, w = threadIdx.x >> 5;
    #pragma unroll
    for (int o = 16; o; o >>= 1) v += __shfl_down_sync(0xffffffffu, v, o);
    if (lane == 0) sh[w] = v;
    __syncthreads();
    if (w == 0) {
        float t = (lane < 8) ? sh[lane] : 0.f;
        #pragma unroll
        for (int o = 4; o; o >>= 1) t += __shfl_down_sync(0xffffffffu, t, o);
        if (lane == 0) sh[0] = t;
    }
    __syncthreads();
    float r = sh[0];
    __syncthreads();
    return r;
}

__device__ __forceinline__ float block_max(float v, float* sh) {
    int lane = threadIdx.x & 31, w = threadIdx.x >> 5;
    #pragma unroll
    for (int o = 16; o; o >>= 1) v = fmaxf(v, __shfl_down_sync(0xffffffffu, v, o));
    if (lane == 0) sh[w] = v;
    __syncthreads();
    if (w == 0) {
        float t = (lane < 8) ? sh[lane] : -3.4e38f;
        #pragma unroll
        for (int o = 4; o; o >>= 1) t = fmaxf(t, __shfl_down_sync(0xffffffffu, t, o));
        if (lane == 0) sh[0] = t;
    }
    __syncthreads();
    float r = sh[0];
    __syncthreads();
    return r;
}

// ---------------- LayerNorm (stores tf32-rounded) ----------------
__global__ __launch_bounds__(256) void ln_kernel(
    const float* __restrict__ in, const float* __restrict__ gamma,
    const float* __restrict__ beta, float* __restrict__ out)
{
    __shared__ float sh[32];
    size_t row = blockIdx.x;
    const float* x = in + row * D_MODEL;
    float v[4], s = 0.f;
    #pragma unroll
    for (int i = 0; i < 4; i++) { v[i] = x[threadIdx.x + i * 256]; s += v[i]; }
    float mean = block_sum(s, sh) * (1.0f / D_MODEL);
    float q = 0.f;
    #pragma unroll
    for (int i = 0; i < 4; i++) { float d = v[i] - mean; q += d * d; }
    float var = block_sum(q, sh) * (1.0f / D_MODEL);
    float rstd = rsqrtf(var + 1e-5f);
    float* y = out + row * D_MODEL;
    #pragma unroll
    for (int i = 0; i < 4; i++) {
        int c = threadIdx.x + i * 256;
        y[c] = tf32r((v[i] - mean) * rstd * gamma[c] + beta[c]);
    }
}

// x kept full precision; norm tf32-rounded
__global__ __launch_bounds__(256) void add_ln_kernel(
    const float* __restrict__ src, const float* __restrict__ attn,
    const float* __restrict__ gamma, const float* __restrict__ beta,
    float* __restrict__ xout, float* __restrict__ nout)
{
    __shared__ float sh[32];
    size_t row = blockIdx.x;
    const float* a = src + row * D_MODEL;
    const float* b = attn + row * D_MODEL;
    float v[4], s = 0.f;
    #pragma unroll
    for (int i = 0; i < 4; i++) {
        int c = threadIdx.x + i * 256;
        v[i] = a[c] + b[c];
        s += v[i];
    }
    float* xo = xout + row * D_MODEL;
    #pragma unroll
    for (int i = 0; i < 4; i++) xo[threadIdx.x + i * 256] = v[i];
    float mean = block_sum(s, sh) * (1.0f / D_MODEL);
    float q = 0.f;
    #pragma unroll
    for (int i = 0; i < 4; i++) { float d = v[i] - mean; q += d * d; }
    float var = block_sum(q, sh) * (1.0f / D_MODEL);
    float rstd = rsqrtf(var + 1e-5f);
    float* y = nout + row * D_MODEL;
    #pragma unroll
    for (int i = 0; i < 4; i++) {
        int c = threadIdx.x + i * 256;
        y[c] = tf32r((v[i] - mean) * rstd * gamma[c] + beta[c]);
    }
}

// ---------------- softmax (stores tf32-rounded) ----------------
__global__ __launch_bounds__(256) void softmax_kernel(float* __restrict__ sc)
{
    __shared__ float sh[32];
    size_t row = blockIdx.x;
    float* p = sc + row * (size_t)SEQ;
    float v[8], m = -3.4e38f;
    #pragma unroll
    for (int i = 0; i < 8; i++) { v[i] = p[threadIdx.x + i * 256]; m = fmaxf(m, v[i]); }
    m = block_max(m, sh);
    float s = 0.f;
    #pragma unroll
    for (int i = 0; i < 8; i++) { v[i] = __expf(v[i] - m); s += v[i]; }
    s = block_sum(s, sh);
    float inv = 1.0f / s;
    #pragma unroll
    for (int i = 0; i < 8; i++) p[threadIdx.x + i * 256] = tf32r(v[i] * inv);
}

// ======================= TF32 tensor-core GEMM (R3 structure) ===============
// Block tile 128x128, BK=8, 128 threads = 4 warps in 2x2, warp tile 64x64.
// mma.sync.m16n8k8.tf32. Double-buffered smem, row stride 136 -> conflict-free.
// Inputs pre-rounded to tf32 by producers; no cvt in this kernel.
// EPI: 0 = scale*AB   1 = gelu(AB + bias) [tf32-rounded]   2 = AB + bias + resid

__device__ __forceinline__ void mma8(float* c, const uint32_t* a, const uint32_t* b) {
    asm volatile(
        "mma.sync.aligned.m16n8k8.row.col.f32.tf32.tf32.f32 "
        "{%0,%1,%2,%3}, {%4,%5,%6,%7}, {%8,%9}, {%0,%1,%2,%3};"
        : "+f"(c[0]), "+f"(c[1]), "+f"(c[2]), "+f"(c[3])
        : "r"(a[0]), "r"(a[1]), "r"(a[2]), "r"(a[3]), "r"(b[0]), "r"(b[1]));
}

__device__ __forceinline__ float gelu_exact(float v) {
    return v * 0.5f * (1.0f + erff(v * 0.70710678118654752f));
}

#define SMS 136   // smem row stride (floats)

template<int TRANS_B, int EPI>
__global__ __launch_bounds__(128) void gemm_tf32(
    const float* __restrict__ A, const float* __restrict__ B, float* __restrict__ C,
    int M, int N, int K, size_t sA, size_t sB, size_t sC,
    const float* __restrict__ bias, const float* __restrict__ resid, float scale)
{
    A += blockIdx.z * sA; B += blockIdx.z * sB; C += blockIdx.z * sC;
    if (EPI == 2) resid += blockIdx.z * sC;

    __shared__ uint32_t As[2][8][SMS];
    __shared__ uint32_t Bs[2][8][SMS];

    const int tid  = threadIdx.x;
    const int lane = tid & 31;
    const int warp = tid >> 5;
    const int warpM = warp >> 1;   // 0..1
    const int warpN = warp & 1;    // 0..1
    const int r  = lane >> 2;      // 0..7
    const int cq = lane & 3;       // 0..3

    const int row0 = blockIdx.y * 128;
    const int col0 = blockIdx.x * 128;

    // ---- global load indexing ----
    const float* pA = A + (size_t)(row0 + tid) * K;

    const float* pB;
    int bkq = 0, bn = 0;
    if (TRANS_B) {
        pB = B + (size_t)(col0 + tid) * K;
    } else {
        bkq = tid >> 4;          // 0..7 : k row
        bn  = (tid & 15) * 4;    // n offset (plus +64 for second quad)
        pB = B + (size_t)bkq * N + col0 + bn;
    }

    float acc[4][8][4] = {};
    float4 fa0, fa1, fb0, fb1;

    auto ldg_tile = [&](int k0) {
        fa0 = *(const float4*)(pA + k0);
        fa1 = *(const float4*)(pA + k0 + 4);
        if (TRANS_B) {
            fb0 = *(const float4*)(pB + k0);
            fb1 = *(const float4*)(pB + k0 + 4);
        } else {
            fb0 = *(const float4*)(pB + (size_t)k0 * N);
            fb1 = *(const float4*)(pB + (size_t)k0 * N + 64);
        }
    };

    auto sts_tile = [&](int nb) {
        float a0[4] = {fa0.x, fa0.y, fa0.z, fa0.w};
        float a1[4] = {fa1.x, fa1.y, fa1.z, fa1.w};
        #pragma unroll
        for (int l = 0; l < 4; l++) {
            As[nb][l][tid]     = __float_as_uint(a0[l]);
            As[nb][4 + l][tid] = __float_as_uint(a1[l]);
        }
        if (TRANS_B) {
            float b0[4] = {fb0.x, fb0.y, fb0.z, fb0.w};
            float b1[4] = {fb1.x, fb1.y, fb1.z, fb1.w};
            #pragma unroll
            for (int l = 0; l < 4; l++) {
                Bs[nb][l][tid]     = __float_as_uint(b0[l]);
                Bs[nb][4 + l][tid] = __float_as_uint(b1[l]);
            }
        } else {
            *(float4*)&Bs[nb][bkq][bn]      = fb0;
            *(float4*)&Bs[nb][bkq][bn + 64] = fb1;
        }
    };

    ldg_tile(0);
    sts_tile(0);
    __syncthreads();

    int buf = 0;
    for (int k0 = 0; k0 < K; k0 += 8) {
        const bool more = (k0 + 8 < K);
        if (more) ldg_tile(k0 + 8);

        // ---- compute on current buffer ----
        uint32_t afr[4][4], bfr[8][2];
        #pragma unroll
        for (int i = 0; i < 4; i++) {
            int m = warpM * 64 + i * 16 + r;
            afr[i][0] = As[buf][cq][m];
            afr[i][1] = As[buf][cq][m + 8];
            afr[i][2] = As[buf][cq + 4][m];
            afr[i][3] = As[buf][cq + 4][m + 8];
        }
        #pragma unroll
        for (int j = 0; j < 8; j++) {
            int n = warpN * 64 + j * 8 + r;
            bfr[j][0] = Bs[buf][cq][n];
            bfr[j][1] = Bs[buf][cq + 4][n];
        }
        #pragma unroll
        for (int i = 0; i < 4; i++)
            #pragma unroll
            for (int j = 0; j < 8; j++)
                mma8(acc[i][j], afr[i], bfr[j]);

        if (more) {
            sts_tile(buf ^ 1);
            __syncthreads();
            buf ^= 1;
        }
    }

    // ---- epilogue ----
    #pragma unroll
    for (int i = 0; i < 4; i++) {
        int mrow = row0 + warpM * 64 + i * 16 + r;
        #pragma unroll
        for (int j = 0; j < 8; j++) {
            int ncol = col0 + warpN * 64 + j * 8 + 2 * cq;
            float v0 = acc[i][j][0], v1 = acc[i][j][1];
            float v2 = acc[i][j][2], v3 = acc[i][j][3];
            if (EPI == 0) {
                v0 *= scale; v1 *= scale; v2 *= scale; v3 *= scale;
            } else {
                float bb0 = bias[ncol], bb1 = bias[ncol + 1];
                if (EPI == 1) {
                    // feeds next GEMM: round to tf32 at store
                    v0 = tf32r(gelu_exact(v0 + bb0)); v1 = tf32r(gelu_exact(v1 + bb1));
                    v2 = tf32r(gelu_exact(v2 + bb0)); v3 = tf32r(gelu_exact(v3 + bb1));
                } else {
                    size_t p0 = (size_t)mrow * N + ncol;
                    size_t p1 = (size_t)(mrow + 8) * N + ncol;
                    v0 += bb0 + resid[p0];     v1 += bb1 + resid[p0 + 1];
                    v2 += bb0 + resid[p1];     v3 += bb1 + resid[p1 + 1];
                }
            }
            size_t p0 = (size_t)mrow * N + ncol;
            size_t p1 = (size_t)(mrow + 8) * N + ncol;
            C[p0] = v0; C[p0 + 1] = v1;
            C[p1] = v2; C[p1 + 1] = v3;
        }
    }
}

// ---------------- launch ----------------
extern "C" void kernel_launch(void* const* d_in, const int* in_sizes, int n_in,
                              void* d_out, int out_size)
{
    const float* src    = (const float*)d_in[0];
    const float* gamma1 = (const float*)d_in[1];
    const float* beta1  = (const float*)d_in[2];
    const float* gamma2 = (const float*)d_in[3];
    const float* beta2  = (const float*)d_in[4];
    const float* w1     = (const float*)d_in[5];
    const float* b1     = (const float*)d_in[6];
    const float* w2     = (const float*)d_in[7];
    const float* b2     = (const float*)d_in[8];
    float* out = (float*)d_out;

    float *norm1, *scores, *attn, *x, *norm2, *h, *w1r, *w2r;
    cudaGetSymbolAddress((void**)&norm1, g_norm1);
    cudaGetSymbolAddress((void**)&scores, g_scores);
    cudaGetSymbolAddress((void**)&attn, g_attn);
    cudaGetSymbolAddress((void**)&x, g_x);
    cudaGetSymbolAddress((void**)&norm2, g_norm2);
    cudaGetSymbolAddress((void**)&h, g_h);
    cudaGetSymbolAddress((void**)&w1r, g_w1r);
    cudaGetSymbolAddress((void**)&w2r, g_w2r);

    const size_t SD = (size_t)SEQ * D_MODEL;
    const size_t SS = (size_t)SEQ * SEQ;

    // 0. tf32-rounded weight copies (same layout, no transpose)
    wrnd_kernel<<<(D_MODEL * D_FF / 4) / 256, 256>>>(w1, w1r, D_MODEL * D_FF);
    wrnd_kernel<<<(D_MODEL * D_FF / 4) / 256, 256>>>(w2, w2r, D_MODEL * D_FF);

    // 1. norm1 = LN(src)  (tf32-rounded)
    ln_kernel<<<NTOK, 256>>>(src, gamma1, beta1, norm1);

    // 2. scores[b] = norm1[b] @ norm1[b]^T / 32
    gemm_tf32<1, 0><<<dim3(SEQ / 128, SEQ / 128, BATCH), 128>>>(
        norm1, norm1, scores, SEQ, SEQ, D_MODEL, SD, SD, SS,
        nullptr, nullptr, 0.03125f);

    // 3. softmax rows (tf32-rounded output)
    softmax_kernel<<<BATCH * SEQ, 256>>>(scores);

    // 4. attn[b] = scores[b] @ norm1[b]
    gemm_tf32<0, 0><<<dim3(D_MODEL / 128, SEQ / 128, BATCH), 128>>>(
        scores, norm1, attn, SEQ, D_MODEL, SEQ, SS, SD, SD,
        nullptr, nullptr, 1.0f);

    // 5. x = src + attn ; norm2 = LN(x)
    add_ln_kernel<<<NTOK, 256>>>(src, attn, gamma2, beta2, x, norm2);

    // 6. h = gelu(norm2 @ w1 + b1)
    gemm_tf32<0, 1><<<dim3(D_FF / 128, NTOK / 128, 1), 128>>>(
        norm2, w1r, h, NTOK, D_FF, D_MODEL, 0, 0, 0, b1, nullptr, 1.0f);

    // 7. out = h @ w2 + b2 + x
    gemm_tf32<0, 2><<<dim3(D_MODEL / 128, NTOK / 128, 1), 128>>>(
        h, w2r, out, NTOK, D_MODEL, D_FF, 0, 0, 0, b2, x, 1.0f);

    (void)in_sizes; (void)n_in; (void)out_size;
}

// round 9
// speedup vs baseline: 1.9472x; 1.6491x over previous
#include <cuda_runtime.h>
#include <cuda_fp16.h>
#include <math.h>
#include <stdint.h>

#define D_MODEL 1024
#define D_FF    4096
#define BATCH   4
#define SEQ     2048
#define NTOK    (BATCH * SEQ)   // 8192

// ---------------- scratch (allocation-free: __device__ globals) ----------------
__device__ __half g_norm1[(size_t)NTOK * D_MODEL];
__device__ __half g_norm1t[(size_t)NTOK * D_MODEL];      // per-batch [D][S]
__device__ __half g_scores[(size_t)BATCH * SEQ * SEQ];   // scores then probs
__device__ float  g_attn[(size_t)NTOK * D_MODEL];
__device__ float  g_x[(size_t)NTOK * D_MODEL];
__device__ __half g_norm2[(size_t)NTOK * D_MODEL];
__device__ __half g_h[(size_t)NTOK * D_FF];
__device__ __half g_w1t[(size_t)D_FF * D_MODEL];         // [ff][d]
__device__ __half g_w2t[(size_t)D_MODEL * D_FF];         // [d][ff]

// ---------------- reductions ----------------
__device__ __forceinline__ float block_sum(float v, float* sh) {
    int lane = threadIdx.x & 31, w = threadIdx.x >> 5;
    #pragma unroll
    for (int o = 16; o; o >>= 1) v += __shfl_down_sync(0xffffffffu, v, o);
    if (lane == 0) sh[w] = v;
    __syncthreads();
    if (w == 0) {
        float t = (lane < 8) ? sh[lane] : 0.f;
        #pragma unroll
        for (int o = 4; o; o >>= 1) t += __shfl_down_sync(0xffffffffu, t, o);
        if (lane == 0) sh[0] = t;
    }
    __syncthreads();
    float r = sh[0];
    __syncthreads();
    return r;
}

__device__ __forceinline__ float block_max(float v, float* sh) {
    int lane = threadIdx.x & 31, w = threadIdx.x >> 5;
    #pragma unroll
    for (int o = 16; o; o >>= 1) v = fmaxf(v, __shfl_down_sync(0xffffffffu, v, o));
    if (lane == 0) sh[w] = v;
    __syncthreads();
    if (w == 0) {
        float t = (lane < 8) ? sh[lane] : -3.4e38f;
        #pragma unroll
        for (int o = 4; o; o >>= 1) t = fmaxf(t, __shfl_down_sync(0xffffffffu, t, o));
        if (lane == 0) sh[0] = t;
    }
    __syncthreads();
    float r = sh[0];
    __syncthreads();
    return r;
}

// ---------------- LayerNorm (fp16 out) ----------------
__global__ __launch_bounds__(256) void ln_kernel(
    const float* __restrict__ in, const float* __restrict__ gamma,
    const float* __restrict__ beta, __half* __restrict__ out)
{
    __shared__ float sh[32];
    size_t row = blockIdx.x;
    const float* x = in + row * D_MODEL;
    float v[4], s = 0.f;
    #pragma unroll
    for (int i = 0; i < 4; i++) { v[i] = x[threadIdx.x + i * 256]; s += v[i]; }
    float mean = block_sum(s, sh) * (1.0f / D_MODEL);
    float q = 0.f;
    #pragma unroll
    for (int i = 0; i < 4; i++) { float d = v[i] - mean; q += d * d; }
    float var = block_sum(q, sh) * (1.0f / D_MODEL);
    float rstd = rsqrtf(var + 1e-5f);
    __half* y = out + row * D_MODEL;
    #pragma unroll
    for (int i = 0; i < 4; i++) {
        int c = threadIdx.x + i * 256;
        y[c] = __float2half_rn((v[i] - mean) * rstd * gamma[c] + beta[c]);
    }
}

// x fp32; norm2 fp16
__global__ __launch_bounds__(256) void add_ln_kernel(
    const float* __restrict__ src, const float* __restrict__ attn,
    const float* __restrict__ gamma, const float* __restrict__ beta,
    float* __restrict__ xout, __half* __restrict__ nout)
{
    __shared__ float sh[32];
    size_t row = blockIdx.x;
    const float* a = src + row * D_MODEL;
    const float* b = attn + row * D_MODEL;
    float v[4], s = 0.f;
    #pragma unroll
    for (int i = 0; i < 4; i++) {
        int c = threadIdx.x + i * 256;
        v[i] = a[c] + b[c];
        s += v[i];
    }
    float* xo = xout + row * D_MODEL;
    #pragma unroll
    for (int i = 0; i < 4; i++) xo[threadIdx.x + i * 256] = v[i];
    float mean = block_sum(s, sh) * (1.0f / D_MODEL);
    float q = 0.f;
    #pragma unroll
    for (int i = 0; i < 4; i++) { float d = v[i] - mean; q += d * d; }
    float var = block_sum(q, sh) * (1.0f / D_MODEL);
    float rstd = rsqrtf(var + 1e-5f);
    __half* y = nout + row * D_MODEL;
    #pragma unroll
    for (int i = 0; i < 4; i++) {
        int c = threadIdx.x + i * 256;
        y[c] = __float2half_rn((v[i] - mean) * rstd * gamma[c] + beta[c]);
    }
}

// ---------------- softmax over fp16 rows of length SEQ (in place) ----------------
__global__ __launch_bounds__(256) void softmax_kernel(__half* __restrict__ sc)
{
    __shared__ float sh[32];
    size_t row = blockIdx.x;
    __half* p = sc + row * (size_t)SEQ;
    float v[8], m = -3.4e38f;
    #pragma unroll
    for (int i = 0; i < 8; i++) { v[i] = __half2float(p[threadIdx.x + i * 256]); m = fmaxf(m, v[i]); }
    m = block_max(m, sh);
    float s = 0.f;
    #pragma unroll
    for (int i = 0; i < 8; i++) { v[i] = __expf(v[i] - m); s += v[i]; }
    s = block_sum(s, sh);
    float inv = 1.0f / s;
    #pragma unroll
    for (int i = 0; i < 8; i++) p[threadIdx.x + i * 256] = __float2half_rn(v[i] * inv);
}

// ---------------- tiled transpose + convert: out[C][R] = cvt(in[R][C])^T ------
template<typename TIN>
__global__ __launch_bounds__(256) void transpose_cvt(
    const TIN* __restrict__ in, __half* __restrict__ out,
    int R, int C, size_t sI, size_t sO)
{
    in += blockIdx.z * sI; out += blockIdx.z * sO;
    __shared__ float t[32][33];
    int tx = threadIdx.x & 31, ty = threadIdx.x >> 5;
    int c = blockIdx.x * 32 + tx;
    int r0 = blockIdx.y * 32;
    #pragma unroll
    for (int i = 0; i < 4; i++)
        t[ty + i * 8][tx] = (float)in[(size_t)(r0 + ty + i * 8) * C + c];
    __syncthreads();
    int rc = r0 + tx;
    int oc0 = blockIdx.x * 32;
    #pragma unroll
    for (int i = 0; i < 4; i++)
        out[(size_t)(oc0 + ty + i * 8) * R + rc] = __float2half_rn(t[tx][ty + i * 8]);
}

// ======================= FP16 HMMA GEMM (NT) ============================
// C[M,N] = A[M,K] @ Bt[N,K]^T, operands fp16, accumulate fp32.
// Block 128x128, 128 threads = 4 warps 2x2, warp tile 64x64,
// mma.sync.m16n8k16, BK=16, double-buffered smem with row stride 12 words
// (16 halves data + 4 words pad): LDS banks (12r+cq)%32 distinct -> CF;
// STS.128 quads (3l)%8 distinct -> CF.
// EPI: 0 = scale*AB -> TOUT   1 = gelu(AB+bias) -> half   2 = AB+bias+resid -> float

__device__ __forceinline__ void mma16(float* c, const uint32_t* a, const uint32_t* b) {
    asm volatile(
        "mma.sync.aligned.m16n8k16.row.col.f32.f16.f16.f32 "
        "{%0,%1,%2,%3}, {%4,%5,%6,%7}, {%8,%9}, {%0,%1,%2,%3};"
        : "+f"(c[0]), "+f"(c[1]), "+f"(c[2]), "+f"(c[3])
        : "r"(a[0]), "r"(a[1]), "r"(a[2]), "r"(a[3]), "r"(b[0]), "r"(b[1]));
}

__device__ __forceinline__ float gelu_exact(float v) {
    return v * 0.5f * (1.0f + erff(v * 0.70710678118654752f));
}

__device__ __forceinline__ void store2(__half* p, float a, float b) {
    *(__half2*)p = __floats2half2_rn(a, b);
}
__device__ __forceinline__ void store2(float* p, float a, float b) {
    p[0] = a; p[1] = b;
}

#define RSTR 12   // smem row stride in 32-bit words

template<int EPI, typename TOUT>
__global__ __launch_bounds__(128) void gemm_f16(
    const __half* __restrict__ A, const __half* __restrict__ Bt, TOUT* __restrict__ C,
    int K, int N, size_t sA, size_t sB, size_t sC,
    const float* __restrict__ bias, const float* __restrict__ resid, float scale)
{
    A += blockIdx.z * sA; Bt += blockIdx.z * sB; C += blockIdx.z * sC;
    if (EPI == 2) resid += blockIdx.z * sC;

    __shared__ uint32_t As[2][128 * RSTR];
    __shared__ uint32_t Bs[2][128 * RSTR];

    const int tid  = threadIdx.x;
    const int lane = tid & 31;
    const int warp = tid >> 5;
    const int warpM = warp >> 1;   // 0..1
    const int warpN = warp & 1;    // 0..1
    const int r  = lane >> 2;      // 0..7
    const int cq = lane & 3;       // 0..3

    const int row0 = blockIdx.y * 128;
    const int col0 = blockIdx.x * 128;

    const __half* pa = A + (size_t)(row0 + tid) * K;
    const __half* pb = Bt + (size_t)(col0 + tid) * K;

    float acc[4][8][4] = {};
    uint4 ra0, ra1, rb0, rb1;

    auto ldg_tile = [&](int c) {
        const uint4* qa = (const uint4*)(pa + c * 16);
        const uint4* qb = (const uint4*)(pb + c * 16);
        ra0 = qa[0]; ra1 = qa[1];
        rb0 = qb[0]; rb1 = qb[1];
    };
    auto sts_tile = [&](int nb) {
        *(uint4*)&As[nb][tid * RSTR]     = ra0;
        *(uint4*)&As[nb][tid * RSTR + 4] = ra1;
        *(uint4*)&Bs[nb][tid * RSTR]     = rb0;
        *(uint4*)&Bs[nb][tid * RSTR + 4] = rb1;
    };

    ldg_tile(0);
    sts_tile(0);
    __syncthreads();

    const int nch = K / 16;
    int buf = 0;
    for (int c = 0; c < nch; c++) {
        const bool more = (c + 1 < nch);
        if (more) ldg_tile(c + 1);

        uint32_t af[4][4], bf[8][2];
        #pragma unroll
        for (int i = 0; i < 4; i++) {
            int m0 = warpM * 64 + i * 16 + r;
            af[i][0] = As[buf][m0 * RSTR + cq];
            af[i][1] = As[buf][(m0 + 8) * RSTR + cq];
            af[i][2] = As[buf][m0 * RSTR + cq + 4];
            af[i][3] = As[buf][(m0 + 8) * RSTR + cq + 4];
        }
        #pragma unroll
        for (int j = 0; j < 8; j++) {
            int n0 = warpN * 64 + j * 8 + r;
            bf[j][0] = Bs[buf][n0 * RSTR + cq];
            bf[j][1] = Bs[buf][n0 * RSTR + cq + 4];
        }
        #pragma unroll
        for (int i = 0; i < 4; i++)
            #pragma unroll
            for (int j = 0; j < 8; j++)
                mma16(acc[i][j], af[i], bf[j]);

        if (more) {
            sts_tile(buf ^ 1);
            __syncthreads();
            buf ^= 1;
        }
    }

    // ---- epilogue ----
    #pragma unroll
    for (int i = 0; i < 4; i++) {
        int mrow = row0 + warpM * 64 + i * 16 + r;
        #pragma unroll
        for (int j = 0; j < 8; j++) {
            int ncol = col0 + warpN * 64 + j * 8 + 2 * cq;
            float v0 = acc[i][j][0], v1 = acc[i][j][1];
            float v2 = acc[i][j][2], v3 = acc[i][j][3];
            size_t p0 = (size_t)mrow * N + ncol;
            size_t p1 = (size_t)(mrow + 8) * N + ncol;
            if (EPI == 0) {
                v0 *= scale; v1 *= scale; v2 *= scale; v3 *= scale;
            } else {
                float bb0 = bias[ncol], bb1 = bias[ncol + 1];
                if (EPI == 1) {
                    v0 = gelu_exact(v0 + bb0); v1 = gelu_exact(v1 + bb1);
                    v2 = gelu_exact(v2 + bb0); v3 = gelu_exact(v3 + bb1);
                } else {
                    v0 += bb0 + resid[p0];     v1 += bb1 + resid[p0 + 1];
                    v2 += bb0 + resid[p1];     v3 += bb1 + resid[p1 + 1];
                }
            }
            store2(C + p0, v0, v1);
            store2(C + p1, v2, v3);
        }
    }
}

// ---------------- launch ----------------
extern "C" void kernel_launch(void* const* d_in, const int* in_sizes, int n_in,
                              void* d_out, int out_size)
{
    const float* src    = (const float*)d_in[0];
    const float* gamma1 = (const float*)d_in[1];
    const float* beta1  = (const float*)d_in[2];
    const float* gamma2 = (const float*)d_in[3];
    const float* beta2  = (const float*)d_in[4];
    const float* w1     = (const float*)d_in[5];
    const float* b1     = (const float*)d_in[6];
    const float* w2     = (const float*)d_in[7];
    const float* b2     = (const float*)d_in[8];
    float* out = (float*)d_out;

    __half *norm1, *norm1t, *scores, *norm2, *h, *w1t, *w2t;
    float *attn, *x;
    cudaGetSymbolAddress((void**)&norm1, g_norm1);
    cudaGetSymbolAddress((void**)&norm1t, g_norm1t);
    cudaGetSymbolAddress((void**)&scores, g_scores);
    cudaGetSymbolAddress((void**)&attn, g_attn);
    cudaGetSymbolAddress((void**)&x, g_x);
    cudaGetSymbolAddress((void**)&norm2, g_norm2);
    cudaGetSymbolAddress((void**)&h, g_h);
    cudaGetSymbolAddress((void**)&w1t, g_w1t);
    cudaGetSymbolAddress((void**)&w2t, g_w2t);

    const size_t SD = (size_t)SEQ * D_MODEL;
    const size_t SS = (size_t)SEQ * SEQ;

    // 0. weight transpose + fp16 convert: w1t[ff][d], w2t[d][ff]
    transpose_cvt<float><<<dim3(D_FF / 32, D_MODEL / 32, 1), 256>>>(w1, w1t, D_MODEL, D_FF, 0, 0);
    transpose_cvt<float><<<dim3(D_MODEL / 32, D_FF / 32, 1), 256>>>(w2, w2t, D_FF, D_MODEL, 0, 0);

    // 1. norm1 = LN(src) -> fp16
    ln_kernel<<<NTOK, 256>>>(src, gamma1, beta1, norm1);

    // 1b. norm1t[b] = norm1[b]^T  ([D][S] per batch, fp16)
    transpose_cvt<__half><<<dim3(D_MODEL / 32, SEQ / 32, BATCH), 256>>>(
        norm1, norm1t, SEQ, D_MODEL, SD, SD);

    // 2. scores[b] = norm1[b] @ norm1[b]^T / 32  -> fp16
    gemm_f16<0, __half><<<dim3(SEQ / 128, SEQ / 128, BATCH), 128>>>(
        norm1, norm1, scores, D_MODEL, SEQ, SD, SD, SS, nullptr, nullptr, 0.03125f);

    // 3. softmax rows (fp16 in/out)
    softmax_kernel<<<BATCH * SEQ, 256>>>(scores);

    // 4. attn[b] = probs[b] @ norm1[b]  (B = norm1t) -> fp32
    gemm_f16<0, float><<<dim3(D_MODEL / 128, SEQ / 128, BATCH), 128>>>(
        scores, norm1t, attn, SEQ, D_MODEL, SS, SD, SD, nullptr, nullptr, 1.0f);

    // 5. x = src + attn ; norm2 = LN(x) -> fp16
    add_ln_kernel<<<NTOK, 256>>>(src, attn, gamma2, beta2, x, norm2);

    // 6. h = gelu(norm2 @ w1 + b1)  (B = w1t) -> fp16
    gemm_f16<1, __half><<<dim3(D_FF / 128, NTOK / 128, 1), 128>>>(
        norm2, w1t, h, D_MODEL, D_FF, 0, 0, 0, b1, nullptr, 1.0f);

    // 7. out = h @ w2 + b2 + x  (B = w2t) -> fp32
    gemm_f16<2, float><<<dim3(D_MODEL / 128, NTOK / 128, 1), 128>>>(
        h, w2t, out, D_FF, D_MODEL, 0, 0, 0, b2, x, 1.0f);

    (void)in_sizes; (void)n_in; (void)out_size;
}

// round 10
// speedup vs baseline: 2.0203x; 1.0376x over previous
#include <cuda_runtime.h>
#include <cuda_fp16.h>
#include <math.h>
#include <stdint.h>

#define D_MODEL 1024
#define D_FF    4096
#define BATCH   4
#define SEQ     2048
#define NTOK    (BATCH * SEQ)   // 8192

// ---------------- scratch (allocation-free: __device__ globals) ----------------
__device__ __half g_norm1[(size_t)NTOK * D_MODEL];
__device__ __half g_norm1t[(size_t)NTOK * D_MODEL];      // per-batch [D][S]
__device__ __half g_scores[(size_t)BATCH * SEQ * SEQ];   // scores then probs
__device__ float  g_attn[(size_t)NTOK * D_MODEL];
__device__ float  g_x[(size_t)NTOK * D_MODEL];
__device__ __half g_norm2[(size_t)NTOK * D_MODEL];
__device__ __half g_h[(size_t)NTOK * D_FF];
__device__ __half g_w1t[(size_t)D_FF * D_MODEL];         // [ff][d]
__device__ __half g_w2t[(size_t)D_MODEL * D_FF];         // [d][ff]

// ---------------- reductions ----------------
__device__ __forceinline__ float block_sum(float v, float* sh) {
    int lane = threadIdx.x & 31, w = threadIdx.x >> 5;
    #pragma unroll
    for (int o = 16; o; o >>= 1) v += __shfl_down_sync(0xffffffffu, v, o);
    if (lane == 0) sh[w] = v;
    __syncthreads();
    if (w == 0) {
        float t = (lane < 8) ? sh[lane] : 0.f;
        #pragma unroll
        for (int o = 4; o; o >>= 1) t += __shfl_down_sync(0xffffffffu, t, o);
        if (lane == 0) sh[0] = t;
    }
    __syncthreads();
    float r = sh[0];
    __syncthreads();
    return r;
}

__device__ __forceinline__ float block_max(float v, float* sh) {
    int lane = threadIdx.x & 31, w = threadIdx.x >> 5;
    #pragma unroll
    for (int o = 16; o; o >>= 1) v = fmaxf(v, __shfl_down_sync(0xffffffffu, v, o));
    if (lane == 0) sh[w] = v;
    __syncthreads();
    if (w == 0) {
        float t = (lane < 8) ? sh[lane] : -3.4e38f;
        #pragma unroll
        for (int o = 4; o; o >>= 1) t = fmaxf(t, __shfl_down_sync(0xffffffffu, t, o));
        if (lane == 0) sh[0] = t;
    }
    __syncthreads();
    float r = sh[0];
    __syncthreads();
    return r;
}

// ---------------- LayerNorm (fp16 out) ----------------
__global__ __launch_bounds__(256) void ln_kernel(
    const float* __restrict__ in, const float* __restrict__ gamma,
    const float* __restrict__ beta, __half* __restrict__ out)
{
    __shared__ float sh[32];
    size_t row = blockIdx.x;
    const float* x = in + row * D_MODEL;
    float v[4], s = 0.f;
    #pragma unroll
    for (int i = 0; i < 4; i++) { v[i] = x[threadIdx.x + i * 256]; s += v[i]; }
    float mean = block_sum(s, sh) * (1.0f / D_MODEL);
    float q = 0.f;
    #pragma unroll
    for (int i = 0; i < 4; i++) { float d = v[i] - mean; q += d * d; }
    float var = block_sum(q, sh) * (1.0f / D_MODEL);
    float rstd = rsqrtf(var + 1e-5f);
    __half* y = out + row * D_MODEL;
    #pragma unroll
    for (int i = 0; i < 4; i++) {
        int c = threadIdx.x + i * 256;
        y[c] = __float2half_rn((v[i] - mean) * rstd * gamma[c] + beta[c]);
    }
}

// x fp32; norm2 fp16
__global__ __launch_bounds__(256) void add_ln_kernel(
    const float* __restrict__ src, const float* __restrict__ attn,
    const float* __restrict__ gamma, const float* __restrict__ beta,
    float* __restrict__ xout, __half* __restrict__ nout)
{
    __shared__ float sh[32];
    size_t row = blockIdx.x;
    const float* a = src + row * D_MODEL;
    const float* b = attn + row * D_MODEL;
    float v[4], s = 0.f;
    #pragma unroll
    for (int i = 0; i < 4; i++) {
        int c = threadIdx.x + i * 256;
        v[i] = a[c] + b[c];
        s += v[i];
    }
    float* xo = xout + row * D_MODEL;
    #pragma unroll
    for (int i = 0; i < 4; i++) xo[threadIdx.x + i * 256] = v[i];
    float mean = block_sum(s, sh) * (1.0f / D_MODEL);
    float q = 0.f;
    #pragma unroll
    for (int i = 0; i < 4; i++) { float d = v[i] - mean; q += d * d; }
    float var = block_sum(q, sh) * (1.0f / D_MODEL);
    float rstd = rsqrtf(var + 1e-5f);
    __half* y = nout + row * D_MODEL;
    #pragma unroll
    for (int i = 0; i < 4; i++) {
        int c = threadIdx.x + i * 256;
        y[c] = __float2half_rn((v[i] - mean) * rstd * gamma[c] + beta[c]);
    }
}

// ---------------- softmax over fp16 rows of length SEQ (in place) ----------------
__global__ __launch_bounds__(256) void softmax_kernel(__half* __restrict__ sc)
{
    __shared__ float sh[32];
    size_t row = blockIdx.x;
    __half* p = sc + row * (size_t)SEQ;
    float v[8], m = -3.4e38f;
    #pragma unroll
    for (int i = 0; i < 8; i++) { v[i] = __half2float(p[threadIdx.x + i * 256]); m = fmaxf(m, v[i]); }
    m = block_max(m, sh);
    float s = 0.f;
    #pragma unroll
    for (int i = 0; i < 8; i++) { v[i] = __expf(v[i] - m); s += v[i]; }
    s = block_sum(s, sh);
    float inv = 1.0f / s;
    #pragma unroll
    for (int i = 0; i < 8; i++) p[threadIdx.x + i * 256] = __float2half_rn(v[i] * inv);
}

// ---------------- tiled transpose + convert: out[C][R] = cvt(in[R][C])^T ------
template<typename TIN>
__global__ __launch_bounds__(256) void transpose_cvt(
    const TIN* __restrict__ in, __half* __restrict__ out,
    int R, int C, size_t sI, size_t sO)
{
    in += blockIdx.z * sI; out += blockIdx.z * sO;
    __shared__ float t[32][33];
    int tx = threadIdx.x & 31, ty = threadIdx.x >> 5;
    int c = blockIdx.x * 32 + tx;
    int r0 = blockIdx.y * 32;
    #pragma unroll
    for (int i = 0; i < 4; i++)
        t[ty + i * 8][tx] = (float)in[(size_t)(r0 + ty + i * 8) * C + c];
    __syncthreads();
    int rc = r0 + tx;
    int oc0 = blockIdx.x * 32;
    #pragma unroll
    for (int i = 0; i < 4; i++)
        out[(size_t)(oc0 + ty + i * 8) * R + rc] = __float2half_rn(t[tx][ty + i * 8]);
}

// ======================= FP16 HMMA GEMM (NT, ldmatrix) ========================
// C[M,N] = A[M,K] @ Bt[N,K]^T, operands fp16, accumulate fp32.
// Block 128x128, 128 threads = 4 warps 2x2, warp tile 64x64,
// mma.sync.m16n8k16, BK=16, double-buffered smem, row stride 12 words.
// Fragment loads via ldmatrix.x4 (4 for A, 4 for B per warp per chunk) —
// conflict-free: banks 12r%32 distinct across each 8-row phase.
// EPI: 0 = scale*AB -> TOUT   1 = gelu(AB+bias) -> half   2 = AB+bias+resid -> float

__device__ __forceinline__ uint32_t smem_u32(const void* p) {
    uint32_t a;
    asm("{ .reg .u64 t; cvta.to.shared.u64 t, %1; cvt.u32.u64 %0, t; }" : "=r"(a) : "l"(p));
    return a;
}

__device__ __forceinline__ void ldsm4(uint32_t& r0, uint32_t& r1, uint32_t& r2, uint32_t& r3,
                                      uint32_t addr) {
    asm volatile("ldmatrix.sync.aligned.m8n8.x4.shared.b16 {%0,%1,%2,%3}, [%4];"
                 : "=r"(r0), "=r"(r1), "=r"(r2), "=r"(r3) : "r"(addr));
}

__device__ __forceinline__ void mma16(float* c, const uint32_t* a, const uint32_t* b) {
    asm volatile(
        "mma.sync.aligned.m16n8k16.row.col.f32.f16.f16.f32 "
        "{%0,%1,%2,%3}, {%4,%5,%6,%7}, {%8,%9}, {%0,%1,%2,%3};"
        : "+f"(c[0]), "+f"(c[1]), "+f"(c[2]), "+f"(c[3])
        : "r"(a[0]), "r"(a[1]), "r"(a[2]), "r"(a[3]), "r"(b[0]), "r"(b[1]));
}

__device__ __forceinline__ float gelu_exact(float v) {
    return v * 0.5f * (1.0f + erff(v * 0.70710678118654752f));
}

__device__ __forceinline__ void store2(__half* p, float a, float b) {
    *(__half2*)p = __floats2half2_rn(a, b);
}
__device__ __forceinline__ void store2(float* p, float a, float b) {
    p[0] = a; p[1] = b;
}

#define RSTR 12                       // smem row stride in 32-bit words
#define TILEW (128 * RSTR)            // words per tile buffer
#define TILEBYTES (TILEW * 4)

template<int EPI, typename TOUT>
__global__ __launch_bounds__(128) void gemm_f16(
    const __half* __restrict__ A, const __half* __restrict__ Bt, TOUT* __restrict__ C,
    int K, int N, size_t sA, size_t sB, size_t sC,
    const float* __restrict__ bias, const float* __restrict__ resid, float scale)
{
    A += blockIdx.z * sA; Bt += blockIdx.z * sB; C += blockIdx.z * sC;
    if (EPI == 2) resid += blockIdx.z * sC;

    __shared__ uint32_t As[2][TILEW];
    __shared__ uint32_t Bs[2][TILEW];

    const int tid  = threadIdx.x;
    const int lane = tid & 31;
    const int warp = tid >> 5;
    const int warpM = warp >> 1;   // 0..1
    const int warpN = warp & 1;    // 0..1
    const int r  = lane >> 2;      // 0..7
    const int cq = lane & 3;       // 0..3

    const int row0 = blockIdx.y * 128;
    const int col0 = blockIdx.x * 128;

    const __half* pa = A + (size_t)(row0 + tid) * K;
    const __half* pb = Bt + (size_t)(col0 + tid) * K;

    // ldmatrix lane addresses (buffer 0); buffer 1 = +TILEBYTES
    const uint32_t asBase = smem_u32(As);
    const uint32_t bsBase = smem_u32(Bs);
    uint32_t aAddr[4], bAddr[4];
    {
        int mrow = (lane & 7) + ((lane >> 3) & 1) * 8;   // row within 16
        int seg  = lane >> 4;                            // k segment 0/1
        #pragma unroll
        for (int i = 0; i < 4; i++) {
            int m = warpM * 64 + i * 16 + mrow;
            aAddr[i] = asBase + (uint32_t)(m * RSTR + seg * 4) * 4;
        }
        int nrow = (lane & 7) + ((lane >> 4) & 1) * 8;   // row within 16 (two j's)
        int bseg = (lane >> 3) & 1;
        #pragma unroll
        for (int jp = 0; jp < 4; jp++) {
            int n = warpN * 64 + jp * 16 + nrow;
            bAddr[jp] = bsBase + (uint32_t)(n * RSTR + bseg * 4) * 4;
        }
    }

    float acc[4][8][4] = {};
    uint4 ra0, ra1, rb0, rb1;

    auto ldg_tile = [&](int c) {
        const uint4* qa = (const uint4*)(pa + c * 16);
        const uint4* qb = (const uint4*)(pb + c * 16);
        ra0 = qa[0]; ra1 = qa[1];
        rb0 = qb[0]; rb1 = qb[1];
    };
    auto sts_tile = [&](int nb) {
        *(uint4*)&As[nb][tid * RSTR]     = ra0;
        *(uint4*)&As[nb][tid * RSTR + 4] = ra1;
        *(uint4*)&Bs[nb][tid * RSTR]     = rb0;
        *(uint4*)&Bs[nb][tid * RSTR + 4] = rb1;
    };

    ldg_tile(0);
    sts_tile(0);
    __syncthreads();

    const int nch = K / 16;
    int buf = 0;
    for (int c = 0; c < nch; c++) {
        const bool more = (c + 1 < nch);
        if (more) ldg_tile(c + 1);

        const uint32_t bo = (uint32_t)buf * TILEBYTES;
        uint32_t af[4][4], bf[8][2];
        #pragma unroll
        for (int i = 0; i < 4; i++)
            ldsm4(af[i][0], af[i][1], af[i][2], af[i][3], aAddr[i] + bo);
        #pragma unroll
        for (int jp = 0; jp < 4; jp++)
            ldsm4(bf[2 * jp][0], bf[2 * jp][1], bf[2 * jp + 1][0], bf[2 * jp + 1][1],
                  bAddr[jp] + bo);

        #pragma unroll
        for (int i = 0; i < 4; i++)
            #pragma unroll
            for (int j = 0; j < 8; j++)
                mma16(acc[i][j], af[i], bf[j]);

        if (more) {
            sts_tile(buf ^ 1);
            __syncthreads();
            buf ^= 1;
        }
    }

    // ---- epilogue ----
    #pragma unroll
    for (int i = 0; i < 4; i++) {
        int mrow = row0 + warpM * 64 + i * 16 + r;
        #pragma unroll
        for (int j = 0; j < 8; j++) {
            int ncol = col0 + warpN * 64 + j * 8 + 2 * cq;
            float v0 = acc[i][j][0], v1 = acc[i][j][1];
            float v2 = acc[i][j][2], v3 = acc[i][j][3];
            size_t p0 = (size_t)mrow * N + ncol;
            size_t p1 = (size_t)(mrow + 8) * N + ncol;
            if (EPI == 0) {
                v0 *= scale; v1 *= scale; v2 *= scale; v3 *= scale;
            } else {
                float bb0 = bias[ncol], bb1 = bias[ncol + 1];
                if (EPI == 1) {
                    v0 = gelu_exact(v0 + bb0); v1 = gelu_exact(v1 + bb1);
                    v2 = gelu_exact(v2 + bb0); v3 = gelu_exact(v3 + bb1);
                } else {
                    v0 += bb0 + resid[p0];     v1 += bb1 + resid[p0 + 1];
                    v2 += bb0 + resid[p1];     v3 += bb1 + resid[p1 + 1];
                }
            }
            store2(C + p0, v0, v1);
            store2(C + p1, v2, v3);
        }
    }
}

// ---------------- launch ----------------
extern "C" void kernel_launch(void* const* d_in, const int* in_sizes, int n_in,
                              void* d_out, int out_size)
{
    const float* src    = (const float*)d_in[0];
    const float* gamma1 = (const float*)d_in[1];
    const float* beta1  = (const float*)d_in[2];
    const float* gamma2 = (const float*)d_in[3];
    const float* beta2  = (const float*)d_in[4];
    const float* w1     = (const float*)d_in[5];
    const float* b1     = (const float*)d_in[6];
    const float* w2     = (const float*)d_in[7];
    const float* b2     = (const float*)d_in[8];
    float* out = (float*)d_out;

    __half *norm1, *norm1t, *scores, *norm2, *h, *w1t, *w2t;
    float *attn, *x;
    cudaGetSymbolAddress((void**)&norm1, g_norm1);
    cudaGetSymbolAddress((void**)&norm1t, g_norm1t);
    cudaGetSymbolAddress((void**)&scores, g_scores);
    cudaGetSymbolAddress((void**)&attn, g_attn);
    cudaGetSymbolAddress((void**)&x, g_x);
    cudaGetSymbolAddress((void**)&norm2, g_norm2);
    cudaGetSymbolAddress((void**)&h, g_h);
    cudaGetSymbolAddress((void**)&w1t, g_w1t);
    cudaGetSymbolAddress((void**)&w2t, g_w2t);

    const size_t SD = (size_t)SEQ * D_MODEL;
    const size_t SS = (size_t)SEQ * SEQ;

    // 0. weight transpose + fp16 convert: w1t[ff][d], w2t[d][ff]
    transpose_cvt<float><<<dim3(D_FF / 32, D_MODEL / 32, 1), 256>>>(w1, w1t, D_MODEL, D_FF, 0, 0);
    transpose_cvt<float><<<dim3(D_MODEL / 32, D_FF / 32, 1), 256>>>(w2, w2t, D_FF, D_MODEL, 0, 0);

    // 1. norm1 = LN(src) -> fp16
    ln_kernel<<<NTOK, 256>>>(src, gamma1, beta1, norm1);

    // 1b. norm1t[b] = norm1[b]^T  ([D][S] per batch, fp16)
    transpose_cvt<__half><<<dim3(D_MODEL / 32, SEQ / 32, BATCH), 256>>>(
        norm1, norm1t, SEQ, D_MODEL, SD, SD);

    // 2. scores[b] = norm1[b] @ norm1[b]^T / 32  -> fp16
    gemm_f16<0, __half><<<dim3(SEQ / 128, SEQ / 128, BATCH), 128>>>(
        norm1, norm1, scores, D_MODEL, SEQ, SD, SD, SS, nullptr, nullptr, 0.03125f);

    // 3. softmax rows (fp16 in/out)
    softmax_kernel<<<BATCH * SEQ, 256>>>(scores);

    // 4. attn[b] = probs[b] @ norm1[b]  (B = norm1t) -> fp32
    gemm_f16<0, float><<<dim3(D_MODEL / 128, SEQ / 128, BATCH), 128>>>(
        scores, norm1t, attn, SEQ, D_MODEL, SS, SD, SD, nullptr, nullptr, 1.0f);

    // 5. x = src + attn ; norm2 = LN(x) -> fp16
    add_ln_kernel<<<NTOK, 256>>>(src, attn, gamma2, beta2, x, norm2);

    // 6. h = gelu(norm2 @ w1 + b1)  (B = w1t) -> fp16
    gemm_f16<1, __half><<<dim3(D_FF / 128, NTOK / 128, 1), 128>>>(
        norm2, w1t, h, D_MODEL, D_FF, 0, 0, 0, b1, nullptr, 1.0f);

    // 7. out = h @ w2 + b2 + x  (B = w2t) -> fp32
    gemm_f16<2, float><<<dim3(D_MODEL / 128, NTOK / 128, 1), 128>>>(
        h, w2t, out, D_FF, D_MODEL, 0, 0, 0, b2, x, 1.0f);

    (void)in_sizes; (void)n_in; (void)out_size;
}

// round 11
// speedup vs baseline: 2.0665x; 1.0228x over previous
#include <cuda_runtime.h>
#include <cuda_fp16.h>
#include <math.h>
#include <stdint.h>

#define D_MODEL 1024
#define D_FF    4096
#define BATCH   4
#define SEQ     2048
#define NTOK    (BATCH * SEQ)   // 8192

// ---------------- scratch (allocation-free: __device__ globals) ----------------
__device__ __half g_norm1[(size_t)NTOK * D_MODEL];
__device__ __half g_norm1t[(size_t)NTOK * D_MODEL];      // per-batch [D][S]
__device__ __half g_scores[(size_t)BATCH * SEQ * SEQ];   // scores then probs
__device__ float  g_attn[(size_t)NTOK * D_MODEL];
__device__ float  g_x[(size_t)NTOK * D_MODEL];
__device__ __half g_norm2[(size_t)NTOK * D_MODEL];
__device__ __half g_h[(size_t)NTOK * D_FF];
__device__ __half g_w1t[(size_t)D_FF * D_MODEL];         // [ff][d]
__device__ __half g_w2t[(size_t)D_MODEL * D_FF];         // [d][ff]

// ---------------- reductions ----------------
__device__ __forceinline__ float block_sum(float v, float* sh) {
    int lane = threadIdx.x & 31, w = threadIdx.x >> 5;
    #pragma unroll
    for (int o = 16; o; o >>= 1) v += __shfl_down_sync(0xffffffffu, v, o);
    if (lane == 0) sh[w] = v;
    __syncthreads();
    if (w == 0) {
        float t = (lane < 8) ? sh[lane] : 0.f;
        #pragma unroll
        for (int o = 4; o; o >>= 1) t += __shfl_down_sync(0xffffffffu, t, o);
        if (lane == 0) sh[0] = t;
    }
    __syncthreads();
    float r = sh[0];
    __syncthreads();
    return r;
}

__device__ __forceinline__ float block_max(float v, float* sh) {
    int lane = threadIdx.x & 31, w = threadIdx.x >> 5;
    #pragma unroll
    for (int o = 16; o; o >>= 1) v = fmaxf(v, __shfl_down_sync(0xffffffffu, v, o));
    if (lane == 0) sh[w] = v;
    __syncthreads();
    if (w == 0) {
        float t = (lane < 8) ? sh[lane] : -3.4e38f;
        #pragma unroll
        for (int o = 4; o; o >>= 1) t = fmaxf(t, __shfl_down_sync(0xffffffffu, t, o));
        if (lane == 0) sh[0] = t;
    }
    __syncthreads();
    float r = sh[0];
    __syncthreads();
    return r;
}

// ---------------- LayerNorm (fp16 out) ----------------
__global__ __launch_bounds__(256) void ln_kernel(
    const float* __restrict__ in, const float* __restrict__ gamma,
    const float* __restrict__ beta, __half* __restrict__ out)
{
    __shared__ float sh[32];
    size_t row = blockIdx.x;
    const float* x = in + row * D_MODEL;
    float v[4], s = 0.f;
    #pragma unroll
    for (int i = 0; i < 4; i++) { v[i] = x[threadIdx.x + i * 256]; s += v[i]; }
    float mean = block_sum(s, sh) * (1.0f / D_MODEL);
    float q = 0.f;
    #pragma unroll
    for (int i = 0; i < 4; i++) { float d = v[i] - mean; q += d * d; }
    float var = block_sum(q, sh) * (1.0f / D_MODEL);
    float rstd = rsqrtf(var + 1e-5f);
    __half* y = out + row * D_MODEL;
    #pragma unroll
    for (int i = 0; i < 4; i++) {
        int c = threadIdx.x + i * 256;
        y[c] = __float2half_rn((v[i] - mean) * rstd * gamma[c] + beta[c]);
    }
}

// x fp32; norm2 fp16
__global__ __launch_bounds__(256) void add_ln_kernel(
    const float* __restrict__ src, const float* __restrict__ attn,
    const float* __restrict__ gamma, const float* __restrict__ beta,
    float* __restrict__ xout, __half* __restrict__ nout)
{
    __shared__ float sh[32];
    size_t row = blockIdx.x;
    const float* a = src + row * D_MODEL;
    const float* b = attn + row * D_MODEL;
    float v[4], s = 0.f;
    #pragma unroll
    for (int i = 0; i < 4; i++) {
        int c = threadIdx.x + i * 256;
        v[i] = a[c] + b[c];
        s += v[i];
    }
    float* xo = xout + row * D_MODEL;
    #pragma unroll
    for (int i = 0; i < 4; i++) xo[threadIdx.x + i * 256] = v[i];
    float mean = block_sum(s, sh) * (1.0f / D_MODEL);
    float q = 0.f;
    #pragma unroll
    for (int i = 0; i < 4; i++) { float d = v[i] - mean; q += d * d; }
    float var = block_sum(q, sh) * (1.0f / D_MODEL);
    float rstd = rsqrtf(var + 1e-5f);
    __half* y = nout + row * D_MODEL;
    #pragma unroll
    for (int i = 0; i < 4; i++) {
        int c = threadIdx.x + i * 256;
        y[c] = __float2half_rn((v[i] - mean) * rstd * gamma[c] + beta[c]);
    }
}

// ---------------- softmax over fp16 rows of length SEQ (in place) ----------------
__global__ __launch_bounds__(256) void softmax_kernel(__half* __restrict__ sc)
{
    __shared__ float sh[32];
    size_t row = blockIdx.x;
    __half* p = sc + row * (size_t)SEQ;
    float v[8], m = -3.4e38f;
    #pragma unroll
    for (int i = 0; i < 8; i++) { v[i] = __half2float(p[threadIdx.x + i * 256]); m = fmaxf(m, v[i]); }
    m = block_max(m, sh);
    float s = 0.f;
    #pragma unroll
    for (int i = 0; i < 8; i++) { v[i] = __expf(v[i] - m); s += v[i]; }
    s = block_sum(s, sh);
    float inv = 1.0f / s;
    #pragma unroll
    for (int i = 0; i < 8; i++) p[threadIdx.x + i * 256] = __float2half_rn(v[i] * inv);
}

// ---------------- tiled transpose + convert: out[C][R] = cvt(in[R][C])^T ------
template<typename TIN>
__global__ __launch_bounds__(256) void transpose_cvt(
    const TIN* __restrict__ in, __half* __restrict__ out,
    int R, int C, size_t sI, size_t sO)
{
    in += blockIdx.z * sI; out += blockIdx.z * sO;
    __shared__ float t[32][33];
    int tx = threadIdx.x & 31, ty = threadIdx.x >> 5;
    int c = blockIdx.x * 32 + tx;
    int r0 = blockIdx.y * 32;
    #pragma unroll
    for (int i = 0; i < 4; i++)
        t[ty + i * 8][tx] = (float)in[(size_t)(r0 + ty + i * 8) * C + c];
    __syncthreads();
    int rc = r0 + tx;
    int oc0 = blockIdx.x * 32;
    #pragma unroll
    for (int i = 0; i < 4; i++)
        out[(size_t)(oc0 + ty + i * 8) * R + rc] = __float2half_rn(t[tx][ty + i * 8]);
}

// ======================= FP16 HMMA GEMM (NT, ldmatrix, BK=32) =================
// C[M,N] = A[M,K] @ Bt[N,K]^T, operands fp16, accumulate fp32.
// Block 128x128, 128 threads = 4 warps 2x2, warp tile 64x64,
// mma.sync.m16n8k16, BK=32 (two k=16 sub-chunks per buffer), double-buffered,
// smem row stride 20 words (32 halves + 4 pad):
//   LDSM phase banks 20r%32 distinct; STS.128 units 5t%8 distinct -> CF.
// EPI: 0 = scale*AB -> TOUT   1 = gelu(AB+bias) -> half   2 = AB+bias+resid -> float

__device__ __forceinline__ uint32_t smem_u32(const void* p) {
    uint32_t a;
    asm("{ .reg .u64 t; cvta.to.shared.u64 t, %1; cvt.u32.u64 %0, t; }" : "=r"(a) : "l"(p));
    return a;
}

__device__ __forceinline__ void ldsm4(uint32_t& r0, uint32_t& r1, uint32_t& r2, uint32_t& r3,
                                      uint32_t addr) {
    asm volatile("ldmatrix.sync.aligned.m8n8.x4.shared.b16 {%0,%1,%2,%3}, [%4];"
                 : "=r"(r0), "=r"(r1), "=r"(r2), "=r"(r3) : "r"(addr));
}

__device__ __forceinline__ void mma16(float* c, const uint32_t* a, const uint32_t* b) {
    asm volatile(
        "mma.sync.aligned.m16n8k16.row.col.f32.f16.f16.f32 "
        "{%0,%1,%2,%3}, {%4,%5,%6,%7}, {%8,%9}, {%0,%1,%2,%3};"
        : "+f"(c[0]), "+f"(c[1]), "+f"(c[2]), "+f"(c[3])
        : "r"(a[0]), "r"(a[1]), "r"(a[2]), "r"(a[3]), "r"(b[0]), "r"(b[1]));
}

__device__ __forceinline__ float gelu_exact(float v) {
    return v * 0.5f * (1.0f + erff(v * 0.70710678118654752f));
}

__device__ __forceinline__ void store2(__half* p, float a, float b) {
    *(__half2*)p = __floats2half2_rn(a, b);
}
__device__ __forceinline__ void store2(float* p, float a, float b) {
    p[0] = a; p[1] = b;
}

#define RSTR 20                       // smem row stride in 32-bit words
#define TILEW (128 * RSTR)            // words per tile buffer
#define TILEBYTES (TILEW * 4)         // 10240

template<int EPI, typename TOUT>
__global__ __launch_bounds__(128) void gemm_f16(
    const __half* __restrict__ A, const __half* __restrict__ Bt, TOUT* __restrict__ C,
    int K, int N, size_t sA, size_t sB, size_t sC,
    const float* __restrict__ bias, const float* __restrict__ resid, float scale)
{
    A += blockIdx.z * sA; Bt += blockIdx.z * sB; C += blockIdx.z * sC;
    if (EPI == 2) resid += blockIdx.z * sC;

    __shared__ uint32_t As[2][TILEW];
    __shared__ uint32_t Bs[2][TILEW];

    const int tid  = threadIdx.x;
    const int lane = tid & 31;
    const int warp = tid >> 5;
    const int warpM = warp >> 1;   // 0..1
    const int warpN = warp & 1;    // 0..1
    const int r  = lane >> 2;      // 0..7
    const int cq = lane & 3;       // 0..3

    const int row0 = blockIdx.y * 128;
    const int col0 = blockIdx.x * 128;

    const __half* pa = A + (size_t)(row0 + tid) * K;
    const __half* pb = Bt + (size_t)(col0 + tid) * K;

    // ldmatrix lane addresses (buffer 0, sub-chunk 0)
    const uint32_t asBase = smem_u32(As);
    const uint32_t bsBase = smem_u32(Bs);
    uint32_t aAddr[4], bAddr[4];
    {
        int mrow = (lane & 7) + ((lane >> 3) & 1) * 8;   // row within 16
        int seg  = lane >> 4;                            // k segment 0/1
        #pragma unroll
        for (int i = 0; i < 4; i++) {
            int m = warpM * 64 + i * 16 + mrow;
            aAddr[i] = asBase + (uint32_t)(m * RSTR + seg * 4) * 4;
        }
        int nrow = (lane & 7) + ((lane >> 4) & 1) * 8;   // row within 16 (two j's)
        int bseg = (lane >> 3) & 1;
        #pragma unroll
        for (int jp = 0; jp < 4; jp++) {
            int n = warpN * 64 + jp * 16 + nrow;
            bAddr[jp] = bsBase + (uint32_t)(n * RSTR + bseg * 4) * 4;
        }
    }

    float acc[4][8][4] = {};
    uint4 ra[4], rb[4];

    auto ldg_tile = [&](int c) {
        const uint4* qa = (const uint4*)(pa + c * 32);
        const uint4* qb = (const uint4*)(pb + c * 32);
        #pragma unroll
        for (int i = 0; i < 4; i++) { ra[i] = qa[i]; rb[i] = qb[i]; }
    };
    auto sts_tile = [&](int nb) {
        #pragma unroll
        for (int i = 0; i < 4; i++) {
            *(uint4*)&As[nb][tid * RSTR + i * 4] = ra[i];
            *(uint4*)&Bs[nb][tid * RSTR + i * 4] = rb[i];
        }
    };

    ldg_tile(0);
    sts_tile(0);
    __syncthreads();

    const int nch = K / 32;
    int buf = 0;
    for (int c = 0; c < nch; c++) {
        const bool more = (c + 1 < nch);
        if (more) ldg_tile(c + 1);

        const uint32_t bo = (uint32_t)buf * TILEBYTES;
        #pragma unroll
        for (int s = 0; s < 2; s++) {
            const uint32_t so = bo + (uint32_t)s * 32;   // +8 words per sub-chunk
            uint32_t af[4][4], bf[8][2];
            #pragma unroll
            for (int i = 0; i < 4; i++)
                ldsm4(af[i][0], af[i][1], af[i][2], af[i][3], aAddr[i] + so);
            #pragma unroll
            for (int jp = 0; jp < 4; jp++)
                ldsm4(bf[2 * jp][0], bf[2 * jp][1], bf[2 * jp + 1][0], bf[2 * jp + 1][1],
                      bAddr[jp] + so);
            #pragma unroll
            for (int i = 0; i < 4; i++)
                #pragma unroll
                for (int j = 0; j < 8; j++)
                    mma16(acc[i][j], af[i], bf[j]);
        }

        if (more) {
            sts_tile(buf ^ 1);
            __syncthreads();
            buf ^= 1;
        }
    }

    // ---- epilogue ----
    #pragma unroll
    for (int i = 0; i < 4; i++) {
        int mrow = row0 + warpM * 64 + i * 16 + r;
        #pragma unroll
        for (int j = 0; j < 8; j++) {
            int ncol = col0 + warpN * 64 + j * 8 + 2 * cq;
            float v0 = acc[i][j][0], v1 = acc[i][j][1];
            float v2 = acc[i][j][2], v3 = acc[i][j][3];
            size_t p0 = (size_t)mrow * N + ncol;
            size_t p1 = (size_t)(mrow + 8) * N + ncol;
            if (EPI == 0) {
                v0 *= scale; v1 *= scale; v2 *= scale; v3 *= scale;
            } else {
                float bb0 = bias[ncol], bb1 = bias[ncol + 1];
                if (EPI == 1) {
                    v0 = gelu_exact(v0 + bb0); v1 = gelu_exact(v1 + bb1);
                    v2 = gelu_exact(v2 + bb0); v3 = gelu_exact(v3 + bb1);
                } else {
                    v0 += bb0 + resid[p0];     v1 += bb1 + resid[p0 + 1];
                    v2 += bb0 + resid[p1];     v3 += bb1 + resid[p1 + 1];
                }
            }
            store2(C + p0, v0, v1);
            store2(C + p1, v2, v3);
        }
    }
}

// ---------------- launch ----------------
extern "C" void kernel_launch(void* const* d_in, const int* in_sizes, int n_in,
                              void* d_out, int out_size)
{
    const float* src    = (const float*)d_in[0];
    const float* gamma1 = (const float*)d_in[1];
    const float* beta1  = (const float*)d_in[2];
    const float* gamma2 = (const float*)d_in[3];
    const float* beta2  = (const float*)d_in[4];
    const float* w1     = (const float*)d_in[5];
    const float* b1     = (const float*)d_in[6];
    const float* w2     = (const float*)d_in[7];
    const float* b2     = (const float*)d_in[8];
    float* out = (float*)d_out;

    __half *norm1, *norm1t, *scores, *norm2, *h, *w1t, *w2t;
    float *attn, *x;
    cudaGetSymbolAddress((void**)&norm1, g_norm1);
    cudaGetSymbolAddress((void**)&norm1t, g_norm1t);
    cudaGetSymbolAddress((void**)&scores, g_scores);
    cudaGetSymbolAddress((void**)&attn, g_attn);
    cudaGetSymbolAddress((void**)&x, g_x);
    cudaGetSymbolAddress((void**)&norm2, g_norm2);
    cudaGetSymbolAddress((void**)&h, g_h);
    cudaGetSymbolAddress((void**)&w1t, g_w1t);
    cudaGetSymbolAddress((void**)&w2t, g_w2t);

    const size_t SD = (size_t)SEQ * D_MODEL;
    const size_t SS = (size_t)SEQ * SEQ;

    // 0. weight transpose + fp16 convert: w1t[ff][d], w2t[d][ff]
    transpose_cvt<float><<<dim3(D_FF / 32, D_MODEL / 32, 1), 256>>>(w1, w1t, D_MODEL, D_FF, 0, 0);
    transpose_cvt<float><<<dim3(D_MODEL / 32, D_FF / 32, 1), 256>>>(w2, w2t, D_FF, D_MODEL, 0, 0);

    // 1. norm1 = LN(src) -> fp16
    ln_kernel<<<NTOK, 256>>>(src, gamma1, beta1, norm1);

    // 1b. norm1t[b] = norm1[b]^T  ([D][S] per batch, fp16)
    transpose_cvt<__half><<<dim3(D_MODEL / 32, SEQ / 32, BATCH), 256>>>(
        norm1, norm1t, SEQ, D_MODEL, SD, SD);

    // 2. scores[b] = norm1[b] @ norm1[b]^T / 32  -> fp16
    gemm_f16<0, __half><<<dim3(SEQ / 128, SEQ / 128, BATCH), 128>>>(
        norm1, norm1, scores, D_MODEL, SEQ, SD, SD, SS, nullptr, nullptr, 0.03125f);

    // 3. softmax rows (fp16 in/out)
    softmax_kernel<<<BATCH * SEQ, 256>>>(scores);

    // 4. attn[b] = probs[b] @ norm1[b]  (B = norm1t) -> fp32
    gemm_f16<0, float><<<dim3(D_MODEL / 128, SEQ / 128, BATCH), 128>>>(
        scores, norm1t, attn, SEQ, D_MODEL, SS, SD, SD, nullptr, nullptr, 1.0f);

    // 5. x = src + attn ; norm2 = LN(x) -> fp16
    add_ln_kernel<<<NTOK, 256>>>(src, attn, gamma2, beta2, x, norm2);

    // 6. h = gelu(norm2 @ w1 + b1)  (B = w1t) -> fp16
    gemm_f16<1, __half><<<dim3(D_FF / 128, NTOK / 128, 1), 128>>>(
        norm2, w1t, h, D_MODEL, D_FF, 0, 0, 0, b1, nullptr, 1.0f);

    // 7. out = h @ w2 + b2 + x  (B = w2t) -> fp32
    gemm_f16<2, float><<<dim3(D_MODEL / 128, NTOK / 128, 1), 128>>>(
        h, w2t, out, D_FF, D_MODEL, 0, 0, 0, b2, x, 1.0f);

    (void)in_sizes; (void)n_in; (void)out_size;
}